// round 9
// baseline (speedup 1.0000x reference)
#include <cuda_runtime.h>

#define NV 23
#define NN 529          // 23*23
#define TV 12
#define ROWLEN 6348     // N*N*T floats per batch
#define MSTRIDE (NV*TV) // 276 floats between consecutive m at fixed i
#define UB 8            // batches in flight per warp
#define GX 256          // x-blocks: 256*8 = 2048 batches per sweep, 16384/2048 = 8 sweeps

__global__ __launch_bounds__(256, 5)
void gat_kernel(const float* __restrict__ flow,
                const int*   __restrict__ adj,
                const float* __restrict__ W,
                float*       __restrict__ out,
                int B)
{
    const int lane = threadIdx.x & 31;
    const int warp = threadIdx.x >> 5;
    const int i    = blockIdx.y * 8 + warp;      // this warp's i index
    if (i >= NV) return;                          // idle warp (i==23): no barriers, safe

    const int k = lane;                           // lane -> k (lanes 23..31 inactive for output)
    const bool act = (k < NV);

    // ---- per-lane attention row att[i][k][0..22] in registers ----
    float att[NV];
    {
        const float* wr = W + (i * NV + (act ? k : 0)) * NV;
        const int*   ar = adj + (act ? k : 0) * NV;
        float mn = 0.0f;                          // = min(min_m W, 0)
        #pragma unroll
        for (int m = 0; m < NV; ++m) {
            att[m] = wr[m];
            mn = fminf(mn, att[m]);
        }
        float s = 0.0f;
        #pragma unroll
        for (int m = 0; m < NV; ++m) {
            int a = ar[m];
            if (k == m) a = 1;                    // forced self-loop
            float v = (a != 0) ? (att[m] - mn) : 0.0f;
            att[m] = v;
            s += v;
        }
        float inv = 1.0f / s;
        #pragma unroll
        for (int m = 0; m < NV; ++m) att[m] *= inv;
    }

    // ---- gather pointer: lane m reads flow[b, m, i, 11]; lanes >=23 clamp to m=22
    const int m_ld = (lane < NV) ? lane : (NV - 1);
    const float* gsrc = flow + m_ld * MSTRIDE + i * TV + (TV - 1);
    float* obase = out + i * NV + k;

    // ---- barrier-free batch loop: 8 independent loads in flight per warp ----
    const int step = GX * UB;
    for (int b0 = blockIdx.x * UB; b0 < B; b0 += step) {

        float v[UB];
        #pragma unroll
        for (int u = 0; u < UB; ++u) {
            const int b = b0 + u;
            v[u] = (b < B) ? __ldg(gsrc + (size_t)b * ROWLEN) : 0.0f;
        }

        #pragma unroll
        for (int u = 0; u < UB; ++u) {
            const int b = b0 + u;
            float acc = 0.0f;
            #pragma unroll
            for (int m = 0; m < NV; ++m) {
                const float dm = __shfl_sync(0xffffffffu, v[u], m);
                acc = fmaf(att[m], dm, acc);
            }
            if (act && b < B)
                obase[(size_t)b * NN] = acc;
        }
    }
}

extern "C" void kernel_launch(void* const* d_in, const int* in_sizes, int n_in,
                              void* d_out, int out_size) {
    const float* flow = (const float*)d_in[0];   // (B, N, N, T) fp32
    const int*   adj  = (const int*)  d_in[1];   // (N, N) int32
    const float* W    = (const float*)d_in[2];   // (N, N, N) fp32
    float*       out  = (float*)d_out;           // (B, N, N, 1) fp32

    const int B = in_sizes[0] / ROWLEN;
    dim3 grid(GX, 3);                            // 3*8 = 24 warps cover i = 0..22 (+1 idle)
    gat_kernel<<<grid, 256>>>(flow, adj, W, out, B);
}